// round 8
// baseline (speedup 1.0000x reference)
#include <cuda_runtime.h>
#include <cuda_bf16.h>

// ConservativeCrossEntropyLoss:
//   loss_i = logsumexp(x_i) - (sum_j w[t_i][j] * x_ij) / S(t_i),  out = mean(loss)
//   w[t][j] = 0.7 (j==t), base + 0.2*2^{t-j} (j>t), base (j<t);  base = 0.1/9
//   S(t) = 0.7 + 8*base + 0.2*(1 - 2^{t-8})
//
// Single persistent kernel: stage 1024-row tiles (36 KB) into smem with 9
// back-to-back float4 loads per thread (MLP=9), compute in 4 stride-9 passes
// (bank-conflict-free), block-reduce, last block folds partials -> out.

#define TPB 256
#define C 9
#define TILE_ROWS 1024                  // 4 rows per thread per tile
#define TILE_F (TILE_ROWS * C)          // 9216 floats
#define TILE_F4 (TILE_F / 4)            // 2304 float4
#define F4_PER_THREAD (TILE_F4 / TPB)   // 9
#define MAX_GRID 2048

__device__ float        g_partials[MAX_GRID];
__device__ unsigned int g_count;        // zero-initialized; reset by last block

__global__ __launch_bounds__(TPB) void cce_fused_kernel(
    const float* __restrict__ logits,
    const int*   __restrict__ targets,
    float*       __restrict__ out,
    int n)
{
    constexpr float BASE   = 0.1f / 9.0f;
    constexpr float MAIN_W = 1.0f - 0.1f - 0.2f;   // 0.7

    __shared__ __align__(16) float tile[TILE_F];   // 36864 B
    __shared__ float s_invS[C];
    __shared__ float s_red[TPB / 32];
    __shared__ int   s_isLast;

    if (threadIdx.x < C) {
        int t = threadIdx.x;
        float p = __int_as_float((127 + t - 8) << 23);   // 2^(t-8), exact
        float S = MAIN_W + 8.0f * BASE + 0.2f * (1.0f - p);
        s_invS[t] = 1.0f / S;
    }

    float acc = 0.0f;
    const int numTiles = (n + TILE_ROWS - 1) / TILE_ROWS;
    const int tid = threadIdx.x;

    for (int tileIdx = blockIdx.x; tileIdx < numTiles; tileIdx += gridDim.x) {
        const int base = tileIdx * TILE_ROWS;
        const int rows = min(TILE_ROWS, n - base);

        __syncthreads();   // smem reuse fence (also orders s_invS init)

        // ---- stage: coalesced, front-batched global -> smem ----
        const float* gsrc = logits + (size_t)base * C;
        if (rows == TILE_ROWS) {
            const float4* __restrict__ g4 = (const float4*)gsrc;
            float4* s4 = (float4*)tile;
            #pragma unroll
            for (int k = 0; k < F4_PER_THREAD; k++)
                s4[tid + k * TPB] = __ldcs(&g4[tid + k * TPB]);
        } else {
            const int nf = rows * C;
            const int nf4 = nf >> 2;
            const float4* __restrict__ g4 = (const float4*)gsrc;
            float4* s4 = (float4*)tile;
            for (int i = tid; i < nf4; i += TPB)
                s4[i] = __ldcs(&g4[i]);
            for (int i = (nf4 << 2) + tid; i < nf; i += TPB)
                tile[i] = __ldcs(&gsrc[i]);
        }
        __syncthreads();

        // ---- compute: 4 passes, one row per thread, stride-9 smem (conflict-free) ----
        #pragma unroll
        for (int p = 0; p < TILE_ROWS / TPB; p++) {
            const int r = p * TPB + tid;
            if (r < rows) {
                const int row = base + r;
                float x[C];
                #pragma unroll
                for (int j = 0; j < C; j++) x[j] = tile[r * C + j];

                float m = x[0];
                #pragma unroll
                for (int j = 1; j < C; j++) m = fmaxf(m, x[j]);

                float s = 0.0f;
                #pragma unroll
                for (int j = 0; j < C; j++) s += __expf(x[j] - m);
                const float lse = m + __logf(s);

                const int t = __ldcs(&targets[row]);
                float dot = 0.0f;
                #pragma unroll
                for (int j = 0; j < C; j++) {
                    const int d = j - t;
                    const float up = 0.2f * __int_as_float((127 - d) << 23); // 2^{-d}, exact
                    float w = (d > 0) ? (BASE + up) : BASE;
                    w = (d == 0) ? MAIN_W : w;
                    dot = fmaf(w, x[j], dot);
                }
                acc += lse - dot * s_invS[t];
            }
        }
    }

    // ---- block reduce (deterministic order) ----
    #pragma unroll
    for (int o = 16; o > 0; o >>= 1)
        acc += __shfl_xor_sync(0xFFFFFFFFu, acc, o);

    const int wid  = tid >> 5;
    const int lane = tid & 31;
    if (lane == 0) s_red[wid] = acc;
    __syncthreads();
    if (wid == 0) {
        float v = (lane < TPB / 32) ? s_red[lane] : 0.0f;
        #pragma unroll
        for (int o = 4; o > 0; o >>= 1)
            v += __shfl_xor_sync(0xFFFFFFFFu, v, o);
        if (lane == 0) {
            g_partials[blockIdx.x] = v;
            __threadfence();
            unsigned int prev = atomicAdd(&g_count, 1u);
            s_isLast = (prev == gridDim.x - 1) ? 1 : 0;
        }
    }
    __syncthreads();

    // ---- last block folds all partials (deterministic index order, fp64) ----
    if (s_isLast) {
        __threadfence();   // acquire: make all blocks' partials visible
        double s = 0.0;
        for (int i = tid; i < (int)gridDim.x; i += TPB)
            s += (double)g_partials[i];

        #pragma unroll
        for (int o = 16; o > 0; o >>= 1)
            s += __shfl_xor_sync(0xFFFFFFFFu, s, o);

        __shared__ double d_red[TPB / 32];
        if (lane == 0) d_red[wid] = s;
        __syncthreads();
        if (wid == 0) {
            double v = (lane < TPB / 32) ? d_red[lane] : 0.0;
            #pragma unroll
            for (int o = 4; o > 0; o >>= 1)
                v += __shfl_xor_sync(0xFFFFFFFFu, v, o);
            if (lane == 0) {
                out[0] = (float)(v / (double)n);
                g_count = 0;          // reset for next graph replay
                __threadfence();
            }
        }
    }
}

extern "C" void kernel_launch(void* const* d_in, const int* in_sizes, int n_in,
                              void* d_out, int out_size)
{
    const float* logits  = (const float*)d_in[0];
    const int*   targets = (const int*)d_in[1];
    const int n = in_sizes[1];                      // row count (targets)

    const int numTiles = (n + TILE_ROWS - 1) / TILE_ROWS;   // 3907 for n=4e6
    int grid = 148 * 6;                             // 6 CTAs/SM (36 KB smem each)
    if (grid > numTiles) grid = numTiles;
    if (grid > MAX_GRID) grid = MAX_GRID;

    cce_fused_kernel<<<grid, TPB>>>(logits, targets, (float*)d_out, n);
}

// round 12
// speedup vs baseline: 1.2812x; 1.2812x over previous
#include <cuda_runtime.h>
#include <cuda_bf16.h>
#include <cstdint>

// ConservativeCrossEntropyLoss:
//   loss_i = logsumexp(x_i) - (sum_j w[t_i][j] * x_ij) / S(t_i),  out = mean(loss)
//   w[t][j] = 0.7 (j==t), base + 0.2*2^{t-j} (j>t), base (j<t);  base = 0.1/9
//   S(t) = 0.7 + 8*base + 0.2*(1 - 2^{t-8})
//
// Single persistent kernel, double-buffered cp.async pipeline:
//   prefetch tile i+2 (async) | compute tile i  -> DRAM never idles at barriers.
// Last block folds per-block partials (fp64) -> out. No second launch.

#define TPB 256
#define C 9
#define TILE_ROWS 512
#define TILE_F   (TILE_ROWS * C)   // 4608 floats = 18432 B
#define TILE_F4  (TILE_F / 4)      // 1152 float4
#define MAX_GRID 2048

__device__ float        g_partials[MAX_GRID];
__device__ unsigned int g_count;    // zero-init; reset by last block each run

__device__ __forceinline__ void cp_async16(uint32_t dst, const float* src) {
    asm volatile("cp.async.cg.shared.global [%0], [%1], 16;" :: "r"(dst), "l"(src));
}
__device__ __forceinline__ void cp_async4(uint32_t dst, const float* src) {
    asm volatile("cp.async.ca.shared.global [%0], [%1], 4;" :: "r"(dst), "l"(src));
}
#define CP_COMMIT() asm volatile("cp.async.commit_group;" ::: "memory")
#define CP_WAIT1()  asm volatile("cp.async.wait_group 1;" ::: "memory")

__device__ __forceinline__ void prefetch_tile(
    const float* __restrict__ logits, int n, int numTiles,
    int tileIdx, uint32_t sbuf, int tid)
{
    if (tileIdx >= numTiles) return;
    const int base = tileIdx * TILE_ROWS;
    const int rows = min(TILE_ROWS, n - base);
    const float* gsrc = logits + (size_t)base * C;
    if (rows == TILE_ROWS) {
        // 1152 float4 / 256 threads = 4 full strides + half stride
        #pragma unroll
        for (int k = 0; k < 4; k++) {
            const int i = tid + k * TPB;
            cp_async16(sbuf + i * 16, gsrc + i * 4);
        }
        if (tid < TILE_F4 - 4 * TPB) {
            const int i = 4 * TPB + tid;
            cp_async16(sbuf + i * 16, gsrc + i * 4);
        }
    } else {
        const int nf  = rows * C;
        const int nf4 = nf >> 2;
        for (int i = tid; i < nf4; i += TPB)
            cp_async16(sbuf + i * 16, gsrc + i * 4);
        for (int i = (nf4 << 2) + tid; i < nf; i += TPB)   // 0-3 tail floats
            cp_async4(sbuf + i * 4, gsrc + i);
    }
}

__global__ __launch_bounds__(TPB, 4) void cce_pipe_kernel(
    const float* __restrict__ logits,
    const int*   __restrict__ targets,
    float*       __restrict__ out,
    int n)
{
    constexpr float BASE   = 0.1f / 9.0f;
    constexpr float MAIN_W = 1.0f - 0.1f - 0.2f;   // 0.7

    __shared__ __align__(16) float tiles[2][TILE_F];   // 36864 B
    __shared__ float s_invS[C];
    __shared__ float s_red[TPB / 32];
    __shared__ int   s_isLast;

    const int tid = threadIdx.x;

    if (tid < C) {
        const int t = tid;
        const float p = __int_as_float((127 + t - 8) << 23);   // 2^(t-8), exact
        s_invS[t] = 1.0f / (MAIN_W + 8.0f * BASE + 0.2f * (1.0f - p));
    }

    const int numTiles = (n + TILE_ROWS - 1) / TILE_ROWS;
    const uint32_t sbase = (uint32_t)__cvta_generic_to_shared(&tiles[0][0]);
    const uint32_t sb0 = sbase, sb1 = sbase + TILE_F * 4;

    // ---- pipeline prologue: 2 tiles in flight ----
    prefetch_tile(logits, n, numTiles, (int)blockIdx.x,                sb0, tid); CP_COMMIT();
    prefetch_tile(logits, n, numTiles, (int)(blockIdx.x + gridDim.x), sb1, tid); CP_COMMIT();

    float acc = 0.0f;
    int buf = 0;
    for (int tileIdx = blockIdx.x; tileIdx < numTiles;
         tileIdx += gridDim.x, buf ^= 1)
    {
        CP_WAIT1();          // oldest group (this buf) complete
        __syncthreads();     // make all threads' copies visible

        const int base = tileIdx * TILE_ROWS;
        const int rows = min(TILE_ROWS, n - base);
        const float* __restrict__ tl = tiles[buf];

        #pragma unroll
        for (int p = 0; p < TILE_ROWS / TPB; p++) {
            const int r = p * TPB + tid;
            if (r < rows) {
                float x[C];
                #pragma unroll
                for (int j = 0; j < C; j++) x[j] = tl[r * C + j];

                float m = x[0], sumx = x[0];
                #pragma unroll
                for (int j = 1; j < C; j++) { m = fmaxf(m, x[j]); sumx += x[j]; }

                float se = 0.0f;
                #pragma unroll
                for (int j = 0; j < C; j++) se += __expf(x[j] - m);
                const float lse = m + __logf(se);

                const int t = __ldcs(&targets[base + r]);
                // dot = BASE*sumx + 0.2*2^t * sum_{j>t} 2^{-j} x_j + (0.7-BASE)*x_t
                float g = 0.0f, xt = 0.0f;
                #pragma unroll
                for (int j = 0; j < C; j++) {
                    const float cj = __int_as_float((127 - j) << 23); // 2^{-j}, literal
                    g  = (j > t)  ? fmaf(cj, x[j], g) : g;
                    xt = (j == t) ? x[j] : xt;
                }
                const float p2t = __int_as_float((127 + t) << 23);     // 2^t
                const float dot = fmaf(BASE, sumx,
                                  fmaf(0.2f * p2t, g, (MAIN_W - BASE) * xt));
                acc += lse - dot * s_invS[t];
            }
        }

        __syncthreads();     // everyone done reading this buf
        prefetch_tile(logits, n, numTiles, tileIdx + 2 * (int)gridDim.x,
                      (buf == 0) ? sb0 : sb1, tid);
        CP_COMMIT();
    }

    // ---- block reduce (deterministic order) ----
    #pragma unroll
    for (int o = 16; o > 0; o >>= 1)
        acc += __shfl_xor_sync(0xFFFFFFFFu, acc, o);

    const int wid  = tid >> 5;
    const int lane = tid & 31;
    if (lane == 0) s_red[wid] = acc;
    __syncthreads();
    if (wid == 0) {
        float v = (lane < TPB / 32) ? s_red[lane] : 0.0f;
        #pragma unroll
        for (int o = 4; o > 0; o >>= 1)
            v += __shfl_xor_sync(0xFFFFFFFFu, v, o);
        if (lane == 0) {
            g_partials[blockIdx.x] = v;
            __threadfence();
            unsigned int prev = atomicAdd(&g_count, 1u);
            s_isLast = (prev == gridDim.x - 1) ? 1 : 0;
        }
    }
    __syncthreads();

    // ---- last block folds all partials (deterministic, fp64) ----
    if (s_isLast) {
        __threadfence();
        double s = 0.0;
        for (int i = tid; i < (int)gridDim.x; i += TPB)
            s += (double)g_partials[i];

        #pragma unroll
        for (int o = 16; o > 0; o >>= 1)
            s += __shfl_xor_sync(0xFFFFFFFFu, s, o);

        __shared__ double d_red[TPB / 32];
        if (lane == 0) d_red[wid] = s;
        __syncthreads();
        if (wid == 0) {
            double v = (lane < TPB / 32) ? d_red[lane] : 0.0;
            #pragma unroll
            for (int o = 4; o > 0; o >>= 1)
                v += __shfl_xor_sync(0xFFFFFFFFu, v, o);
            if (lane == 0) {
                out[0] = (float)(v / (double)n);
                g_count = 0;          // reset for next graph replay
                __threadfence();
            }
        }
    }
}

extern "C" void kernel_launch(void* const* d_in, const int* in_sizes, int n_in,
                              void* d_out, int out_size)
{
    const float* logits  = (const float*)d_in[0];
    const int*   targets = (const int*)d_in[1];
    const int n = in_sizes[1];                      // row count (targets)

    const int numTiles = (n + TILE_ROWS - 1) / TILE_ROWS;   // 7813 for n=4e6
    int grid = 148 * 4;                             // 4 CTAs/SM (reg-honest)
    if (grid > numTiles) grid = numTiles;
    if (grid > MAX_GRID) grid = MAX_GRID;

    cce_pipe_kernel<<<grid, TPB>>>(logits, targets, (float*)d_out, n);
}

// round 13
// speedup vs baseline: 1.4230x; 1.1107x over previous
#include <cuda_runtime.h>
#include <cuda_bf16.h>
#include <cstdint>

// ConservativeCrossEntropyLoss:
//   loss_i = logsumexp(x_i) - sum_j wn[t_i][j] * x_ij,  out = mean(loss)
//   wn[t][j] = w[t][j]/S(t);  w[t][j] = 0.7 (j==t), base+0.2*2^{t-j} (j>t), base (j<t)
//   base = 0.1/9;  S(t) = 0.7 + 8*base + 0.2*(1 - 2^{t-8})
//
// Persistent kernel, 3-buffer cp.async ring (2 tiles always in flight),
// 6 CTAs/SM, normalized-weight LUT in smem (conflict-free by bank math).
// Last block folds per-block partials (fp64) -> out. Single launch.

#define TPB 256
#define C 9
#define TILE_ROWS 256
#define TILE_F   (TILE_ROWS * C)   // 2304 floats = 9216 B
#define TILE_F4  (TILE_F / 4)      // 576 float4
#define NBUF 3
#define MAX_GRID 2048

__device__ float        g_partials[MAX_GRID];
__device__ unsigned int g_count;    // zero-init; reset by last block each run

__device__ __forceinline__ void cp_async16(uint32_t dst, const float* src) {
    asm volatile("cp.async.cg.shared.global [%0], [%1], 16;" :: "r"(dst), "l"(src));
}
__device__ __forceinline__ void cp_async4(uint32_t dst, const float* src) {
    asm volatile("cp.async.ca.shared.global [%0], [%1], 4;" :: "r"(dst), "l"(src));
}
#define CP_COMMIT() asm volatile("cp.async.commit_group;" ::: "memory")
#define CP_WAIT2()  asm volatile("cp.async.wait_group 2;" ::: "memory")

__device__ __forceinline__ void prefetch_tile(
    const float* __restrict__ logits, int n, int numTiles,
    int tileIdx, uint32_t sbuf, int tid)
{
    if (tileIdx >= numTiles) return;
    const int base = tileIdx * TILE_ROWS;
    const int rows = min(TILE_ROWS, n - base);
    const float* gsrc = logits + (size_t)base * C;
    if (rows == TILE_ROWS) {
        // 576 float4 / 256 threads: 2 full strides + 64
        cp_async16(sbuf + tid * 16,              gsrc + tid * 4);
        cp_async16(sbuf + (tid + TPB) * 16,      gsrc + (tid + TPB) * 4);
        if (tid < TILE_F4 - 2 * TPB)
            cp_async16(sbuf + (tid + 2 * TPB) * 16, gsrc + (tid + 2 * TPB) * 4);
    } else {
        const int nf  = rows * C;
        const int nf4 = nf >> 2;
        for (int i = tid; i < nf4; i += TPB)
            cp_async16(sbuf + i * 16, gsrc + i * 4);
        for (int i = (nf4 << 2) + tid; i < nf; i += TPB)
            cp_async4(sbuf + i * 4, gsrc + i);
    }
}

__global__ __launch_bounds__(TPB, 6) void cce_ring_kernel(
    const float* __restrict__ logits,
    const int*   __restrict__ targets,
    float*       __restrict__ out,
    int n)
{
    constexpr float BASE   = 0.1f / 9.0f;
    constexpr float MAIN_W = 1.0f - 0.1f - 0.2f;   // 0.7

    __shared__ __align__(16) float tiles[NBUF][TILE_F];   // 27648 B
    __shared__ float s_wn[C * C];                          // normalized weights
    __shared__ float s_red[TPB / 32];
    __shared__ int   s_isLast;

    const int tid = threadIdx.x;

    // ---- build normalized-weight LUT: wn[t][j] = w[t][j] / S(t) ----
    if (tid < C * C) {
        const int t = tid / C, j = tid % C;
        const int d = j - t;
        const float up = (d > 0) ? 0.2f * __int_as_float((127 - d) << 23) : 0.0f;
        float w = (d == 0) ? MAIN_W : (BASE + up);
        const float p = __int_as_float((127 + t - 8) << 23);            // 2^(t-8)
        const float S = MAIN_W + 8.0f * BASE + 0.2f * (1.0f - p);
        s_wn[tid] = w / S;
    }

    const int numTiles = (n + TILE_ROWS - 1) / TILE_ROWS;
    const uint32_t sbase = (uint32_t)__cvta_generic_to_shared(&tiles[0][0]);

    // ---- prologue: fill the ring ----
    #pragma unroll
    for (int k = 0; k < NBUF; k++) {
        prefetch_tile(logits, n, numTiles, (int)(blockIdx.x + k * gridDim.x),
                      sbase + k * (TILE_F * 4), tid);
        CP_COMMIT();
    }

    float acc = 0.0f;
    int buf = 0;
    for (int tileIdx = blockIdx.x; tileIdx < numTiles;
         tileIdx += gridDim.x, buf = (buf == NBUF - 1) ? 0 : buf + 1)
    {
        CP_WAIT2();          // oldest group (this buf) complete; 2 stay in flight
        __syncthreads();     // copies visible to all (also orders LUT init)

        const int base = tileIdx * TILE_ROWS;
        const int rows = min(TILE_ROWS, n - base);
        const float* __restrict__ tl = tiles[buf];

        if (tid < rows) {
            float x[C];
            #pragma unroll
            for (int j = 0; j < C; j++) x[j] = tl[tid * C + j];

            float m = x[0];
            #pragma unroll
            for (int j = 1; j < C; j++) m = fmaxf(m, x[j]);

            float se = 0.0f;
            #pragma unroll
            for (int j = 0; j < C; j++) se += __expf(x[j] - m);
            const float lse = m + __logf(se);

            const int t = __ldcs(&targets[base + tid]);
            const float* __restrict__ wr = &s_wn[t * C];   // lane-varying t: conflict-free
            float dot = 0.0f;
            #pragma unroll
            for (int j = 0; j < C; j++) dot = fmaf(wr[j], x[j], dot);

            acc += lse - dot;
        }

        __syncthreads();     // everyone done reading this buf
        prefetch_tile(logits, n, numTiles, tileIdx + NBUF * (int)gridDim.x,
                      sbase + buf * (TILE_F * 4), tid);
        CP_COMMIT();
    }

    // ---- block reduce (deterministic order) ----
    #pragma unroll
    for (int o = 16; o > 0; o >>= 1)
        acc += __shfl_xor_sync(0xFFFFFFFFu, acc, o);

    const int wid  = tid >> 5;
    const int lane = tid & 31;
    if (lane == 0) s_red[wid] = acc;
    __syncthreads();
    if (wid == 0) {
        float v = (lane < TPB / 32) ? s_red[lane] : 0.0f;
        #pragma unroll
        for (int o = 4; o > 0; o >>= 1)
            v += __shfl_xor_sync(0xFFFFFFFFu, v, o);
        if (lane == 0) {
            g_partials[blockIdx.x] = v;
            __threadfence();
            unsigned int prev = atomicAdd(&g_count, 1u);
            s_isLast = (prev == gridDim.x - 1) ? 1 : 0;
        }
    }
    __syncthreads();

    // ---- last block folds all partials (deterministic, fp64) ----
    if (s_isLast) {
        __threadfence();
        double s = 0.0;
        for (int i = tid; i < (int)gridDim.x; i += TPB)
            s += (double)g_partials[i];

        #pragma unroll
        for (int o = 16; o > 0; o >>= 1)
            s += __shfl_xor_sync(0xFFFFFFFFu, s, o);

        __shared__ double d_red[TPB / 32];
        if (lane == 0) d_red[wid] = s;
        __syncthreads();
        if (wid == 0) {
            double v = (lane < TPB / 32) ? d_red[lane] : 0.0;
            #pragma unroll
            for (int o = 4; o > 0; o >>= 1)
                v += __shfl_xor_sync(0xFFFFFFFFu, v, o);
            if (lane == 0) {
                out[0] = (float)(v / (double)n);
                g_count = 0;          // reset for next graph replay
                __threadfence();
            }
        }
    }
}

extern "C" void kernel_launch(void* const* d_in, const int* in_sizes, int n_in,
                              void* d_out, int out_size)
{
    const float* logits  = (const float*)d_in[0];
    const int*   targets = (const int*)d_in[1];
    const int n = in_sizes[1];                      // row count (targets)

    const int numTiles = (n + TILE_ROWS - 1) / TILE_ROWS;   // 15625 for n=4e6
    int grid = 148 * 6;                             // 6 CTAs/SM (27.6 KB smem each)
    if (grid > numTiles) grid = numTiles;
    if (grid > MAX_GRID) grid = MAX_GRID;

    cce_ring_kernel<<<grid, TPB>>>(logits, targets, (float*)d_out, n);
}